// round 14
// baseline (speedup 1.0000x reference)
#include <cuda_runtime.h>
#include <cuda_bf16.h>
#include <cstdint>

#define BLOCK 256
#define ROWS 8
#define HALF 2560          // max sources staged per block (column split)
#define MAXM 5120

// ---------- packed f32x2 helpers (Blackwell) ----------
__device__ __forceinline__ uint64_t pk2(float x, float y) {
    uint64_t r; asm("mov.b64 %0, {%1, %2};" : "=l"(r) : "f"(x), "f"(y)); return r;
}
__device__ __forceinline__ void upk2(uint64_t v, float& x, float& y) {
    asm("mov.b64 {%0, %1}, %2;" : "=f"(x), "=f"(y) : "l"(v));
}
__device__ __forceinline__ uint64_t add2(uint64_t a, uint64_t b) {
    uint64_t d; asm("add.rn.f32x2 %0, %1, %2;" : "=l"(d) : "l"(a), "l"(b)); return d;
}
__device__ __forceinline__ uint64_t mul2(uint64_t a, uint64_t b) {
    uint64_t d; asm("mul.rn.f32x2 %0, %1, %2;" : "=l"(d) : "l"(a), "l"(b)); return d;
}
__device__ __forceinline__ uint64_t fma2(uint64_t a, uint64_t b, uint64_t c) {
    uint64_t d; asm("fma.rn.f32x2 %0, %1, %2, %3;" : "=l"(d) : "l"(a), "l"(b), "l"(c)); return d;
}
__device__ __forceinline__ uint64_t c2(float k) { return pk2(k, k); }

// ---------- scalar approx primitives ----------
__device__ __forceinline__ float rsq_ap(float x){ float y; asm("rsqrt.approx.f32 %0, %1;" : "=f"(y) : "f"(x)); return y; }
__device__ __forceinline__ float sqrt_ap(float x){ float y; asm("sqrt.approx.f32 %0, %1;" : "=f"(y) : "f"(x)); return y; }
__device__ __forceinline__ float cos_ap(float x){ float y; asm("cos.approx.f32 %0, %1;" : "=f"(y) : "f"(x)); return y; }
__device__ __forceinline__ float rcp_ap(float x){ float y; asm("rcp.approx.f32 %0, %1;" : "=f"(y) : "f"(x)); return y; }

// ---------- constants ----------
#define INV2PI  0.15915494309189535f
#define NC1     (-6.28125f)
#define NC2     (-1.9353071795864769e-3f)
#define SMALLS  (6.4e-5f)               // (8/1000)^2 : ax<8  <=>  s<SMALLS
// folded constants (computed in double):
#define CSQA    (4.0156892e-3f)         // sqrt(0.636619772e-3 / (2pi)^2)
#define CQZ     (-1.2499999960e-4f)     // Q0C * 8e-3
#define CPA     (-2.823524e-10f)        // P1C * 6.4e-5 * CSQA
#define CPB     (4.497788e-16f)         // P2C * (6.4e-5)^2 * CSQA

// ---------- accurate scalar fallback (rare small-argument groups) ----------
__device__ __noinline__ float j0_slow(float dx, float dy) {
    float s  = fmaf(dx, dx, dy * dy);
    float r  = __fsqrt_rn(s);
    float ax = 1000.0f * r;
    float res;
    if (ax < 8.0f) {
        float y = ax * ax;
        float num = fmaf(y, fmaf(y, fmaf(y, fmaf(y, fmaf(y, -184.9052456f,
                        77392.33017f), -11214424.18f), 651619640.7f),
                        -13362590354.0f), 57568490574.0f);
        float den = fmaf(y, fmaf(y, fmaf(y, fmaf(y, fmaf(y, 1.0f,
                        267.8532712f), 59272.64853f), 9494680.718f),
                        1029532985.0f), 57568490411.0f);
        res = num * rcp_ap(den);
    } else {
        float inv = rcp_ap(ax);
        float z   = 8.0f * inv;
        float y2  = z * z;
        float xx  = ax - 0.785398164f;
        float qn  = rintf(xx * INV2PI);
        float t   = fmaf(qn, NC1, xx);
        t         = fmaf(qn, NC2, t);
        float sn = __sinf(t);
        float cs = __cosf(t);
        float p0 = fmaf(y2, fmaf(y2, fmaf(y2, fmaf(y2, 0.2093887211e-6f,
                        -0.2073370639e-5f), 0.2734510407e-4f),
                        -0.1098628627e-2f), 1.0f);
        float q0 = fmaf(y2, fmaf(y2, fmaf(y2, fmaf(y2, -0.934935152e-7f,
                        0.7621095161e-6f), -0.6911147651e-5f),
                        0.1430488765e-3f), -0.1562499995e-1f);
        float amp = sqrt_ap(0.636619772f * inv);
        res = amp * fmaf(cs, p0, -(z * sn * q0));
    }
    return res * INV2PI;
}

// Fused fast path for a packed pair. Requires both s >= SMALLS.
// amp = r^{-1/2} via bit-trick seed + 2 packed Newton steps (no MUFU).
__device__ __forceinline__ uint64_t pair_fast(uint64_t s) {
    float s0, s1; upk2(s, s0, s1);
    uint64_t i0 = pk2(rsq_ap(s0), rsq_ap(s1));        // ~1/sqrt(s)  [2 MUFU]
    uint64_t r0 = mul2(s, i0);                        // ~sqrt(s)
    uint64_t d  = fma2(i0, r0, c2(-1.0f));            // s*i0^2 - 1 (FMA-exact)
    uint64_t w  = mul2(r0, d);
    uint64_t r  = fma2(w, c2(-0.5f), r0);             // refined sqrt(s)
    uint64_t xx = fma2(r, c2(1000.0f), c2(-0.785398164f));
    uint64_t tp = fma2(i0, c2(CQZ), xx);              // + z*q0 phase fold
    uint64_t ii = mul2(i0, i0);
    uint64_t p0 = fma2(ii, fma2(ii, c2(CPB), c2(CPA)), c2(CSQA)); // SQA*p0
    // ---- amp = r^{-1/2}: magic seed (ALU) + 2 packed Newton steps (FMA) ----
    uint32_t rl = (uint32_t)r, rh = (uint32_t)(r >> 32);
    uint64_t y  = (uint64_t)(0x5f375a86u - (rl >> 1))
                | ((uint64_t)(0x5f375a86u - (rh >> 1)) << 32);
    uint64_t hr = mul2(r, c2(-0.5f));
    uint64_t yy = mul2(y, y);
    y = mul2(y, fma2(hr, yy, c2(1.5f)));
    yy = mul2(y, y);
    y = mul2(y, fma2(hr, yy, c2(1.5f)));              // rel err ~3e-7
    // ---- cos (HW range reduction) and combine ----
    float t0, t1; upk2(tp, t0, t1);
    uint64_t cs = pk2(cos_ap(t0), cos_ap(t1));        // [2 MUFU]
    uint64_t pc = mul2(p0, cs);
    return mul2(y, pc);
}

// One 4-column group. Slow path recomputes coords from px/py (keeps the
// packed diffs' live ranges out of the branch — measured best structure).
__device__ __forceinline__ ulonglong2 group4p(ulonglong2 ux, ulonglong2 uy,
                                              uint64_t npx, uint64_t npy,
                                              float px, float py) {
    uint64_t dxA = add2(ux.x, npx);
    uint64_t dyA = add2(uy.x, npy);
    uint64_t dxB = add2(ux.y, npx);
    uint64_t dyB = add2(uy.y, npy);
    uint64_t sA = fma2(dxA, dxA, mul2(dyA, dyA));
    uint64_t sB = fma2(dxB, dxB, mul2(dyB, dyB));
    float s0, s1, s2, s3;
    upk2(sA, s0, s1); upk2(sB, s2, s3);
    ulonglong2 o;
    if (__builtin_expect(fminf(fminf(s0, s1), fminf(s2, s3)) < SMALLS, 0)) {
        float x0, x1, x2, x3, y0, y1, y2, y3;
        upk2(ux.x, x0, x1); upk2(ux.y, x2, x3);
        upk2(uy.x, y0, y1); upk2(uy.y, y2, y3);
        o.x = pk2(j0_slow(px - x0, py - y0), j0_slow(px - x1, py - y1));
        o.y = pk2(j0_slow(px - x2, py - y2), j0_slow(px - x3, py - y3));
    } else {
        o.x = pair_fast(sA);
        o.y = pair_fast(sB);
    }
    return o;
}

// Column-split kernel: gridDim.y=2 halves of the source set, 20 KB smem each,
// 6 blocks/SM. 2 rows x 4 cols micro-tile, 128-bit LDS/STG end-to-end.
__global__ __launch_bounds__(BLOCK, 6)
void pikf_packed_kernel(const float2* __restrict__ p,
                        const float2* __restrict__ src,
                        float* __restrict__ out, int N, int M, int chunk) {
    __shared__ float sx[HALF];
    __shared__ float sy[HALF];

    const int base = blockIdx.y * chunk;
    const int cnt  = min(chunk, M - base);
    for (int i = threadIdx.x; i < cnt; i += BLOCK) {
        float2 v = src[base + i];
        sx[i] = v.x;
        sy[i] = v.y;
    }
    __syncthreads();

    const int C4 = cnt >> 2;
    const ulonglong2* sx4 = (const ulonglong2*)sx;
    const ulonglong2* sy4 = (const ulonglong2*)sy;

    const int row0 = blockIdx.x * ROWS;
    #pragma unroll 1
    for (int rp = 0; rp < ROWS / 2; ++rp) {
        int n0 = row0 + rp * 2;
        if (n0 >= N) return;
        int n1 = n0 + 1;
        float2 pp0 = p[n0];
        uint64_t npx0 = c2(-pp0.x), npy0 = c2(-pp0.y);
        ulonglong2* o40 = (ulonglong2*)(out + (size_t)n0 * M + base);

        if (n1 < N) {
            float2 pp1 = p[n1];
            uint64_t npx1 = c2(-pp1.x), npy1 = c2(-pp1.y);
            ulonglong2* o41 = (ulonglong2*)(out + (size_t)n1 * M + base);
            #pragma unroll 2
            for (int j = threadIdx.x; j < C4; j += BLOCK) {
                ulonglong2 ux = sx4[j];
                ulonglong2 uy = sy4[j];
                o40[j] = group4p(ux, uy, npx0, npy0, pp0.x, pp0.y);
                o41[j] = group4p(ux, uy, npx1, npy1, pp1.x, pp1.y);
            }
        } else {
            for (int j = threadIdx.x; j < C4; j += BLOCK) {
                ulonglong2 ux = sx4[j];
                ulonglong2 uy = sy4[j];
                o40[j] = group4p(ux, uy, npx0, npy0, pp0.x, pp0.y);
            }
        }
    }
}

// scalar fallback for odd M / huge M
__global__ __launch_bounds__(BLOCK)
void pikf_scalar_kernel(const float2* __restrict__ p,
                        const float2* __restrict__ src,
                        float* __restrict__ out, int N, int M) {
    int row0 = blockIdx.x * ROWS;
    for (int rr = 0; rr < ROWS; ++rr) {
        int n = row0 + rr;
        if (n >= N) return;
        float2 pp = p[n];
        for (int m = threadIdx.x; m < M; m += BLOCK) {
            float2 v = __ldg(&src[m]);
            out[(size_t)n * M + m] = j0_slow(pp.x - v.x, pp.y - v.y);
        }
    }
}

extern "C" void kernel_launch(void* const* d_in, const int* in_sizes, int n_in,
                              void* d_out, int out_size) {
    const float2* p   = (const float2*)d_in[0];
    const float2* src = (const float2*)d_in[1];
    float* out = (float*)d_out;
    int N = in_sizes[0] / 2;
    int M = in_sizes[1] / 2;
    int gx = (N + ROWS - 1) / ROWS;
    // column split into 2 chunks; M % 8 == 0 keeps both halves 16B-aligned.
    if (M <= MAXM && (M % 8) == 0 && (M / 2) <= HALF) {
        int chunk = M / 2;
        dim3 grid(gx, 2);
        pikf_packed_kernel<<<grid, BLOCK>>>(p, src, out, N, M, chunk);
    } else {
        pikf_scalar_kernel<<<gx, BLOCK>>>(p, src, out, N, M);
    }
}

// round 15
// speedup vs baseline: 1.1756x; 1.1756x over previous
#include <cuda_runtime.h>
#include <cuda_bf16.h>
#include <cstdint>

#define BLOCK 256
#define ROWS 8
#define HALF 2560          // max sources staged per block (column split)
#define MAXM 5120

// ---------- packed f32x2 helpers (Blackwell) ----------
__device__ __forceinline__ uint64_t pk2(float x, float y) {
    uint64_t r; asm("mov.b64 %0, {%1, %2};" : "=l"(r) : "f"(x), "f"(y)); return r;
}
__device__ __forceinline__ void upk2(uint64_t v, float& x, float& y) {
    asm("mov.b64 {%0, %1}, %2;" : "=f"(x), "=f"(y) : "l"(v));
}
__device__ __forceinline__ uint64_t add2(uint64_t a, uint64_t b) {
    uint64_t d; asm("add.rn.f32x2 %0, %1, %2;" : "=l"(d) : "l"(a), "l"(b)); return d;
}
__device__ __forceinline__ uint64_t mul2(uint64_t a, uint64_t b) {
    uint64_t d; asm("mul.rn.f32x2 %0, %1, %2;" : "=l"(d) : "l"(a), "l"(b)); return d;
}
__device__ __forceinline__ uint64_t fma2(uint64_t a, uint64_t b, uint64_t c) {
    uint64_t d; asm("fma.rn.f32x2 %0, %1, %2, %3;" : "=l"(d) : "l"(a), "l"(b), "l"(c)); return d;
}
__device__ __forceinline__ uint64_t c2(float k) { return pk2(k, k); }

// ---------- scalar approx primitives ----------
__device__ __forceinline__ float rsq_ap(float x){ float y; asm("rsqrt.approx.f32 %0, %1;" : "=f"(y) : "f"(x)); return y; }
__device__ __forceinline__ float sqrt_ap(float x){ float y; asm("sqrt.approx.f32 %0, %1;" : "=f"(y) : "f"(x)); return y; }
__device__ __forceinline__ float cos_ap(float x){ float y; asm("cos.approx.f32 %0, %1;" : "=f"(y) : "f"(x)); return y; }
__device__ __forceinline__ float rcp_ap(float x){ float y; asm("rcp.approx.f32 %0, %1;" : "=f"(y) : "f"(x)); return y; }

// ---------- constants ----------
#define INV2PI  0.15915494309189535f
#define NC1     (-6.28125f)
#define NC2     (-1.9353071795864769e-3f)
#define SMALLS  (6.4e-5f)               // (8/1000)^2 : ax<8  <=>  s<SMALLS
#define CQZ     (-1.2499999960e-4f)     // Q0C * 8e-3 (phase-folded quadrature)
// CSQA = sqrt(0.636619772e-3)/(2pi) = 4.0156892e-3 ; amplitude folded into
// the rsqrt argument: CSQA * r^{-1/2} = rsqrt(r * CINV), CINV = 1/CSQA^2.
#define CINV    (62012.47f)

// ---------- accurate scalar fallback (rare small-argument groups) ----------
__device__ __noinline__ float j0_slow(float dx, float dy) {
    float s  = fmaf(dx, dx, dy * dy);
    float r  = __fsqrt_rn(s);
    float ax = 1000.0f * r;
    float res;
    if (ax < 8.0f) {
        float y = ax * ax;
        float num = fmaf(y, fmaf(y, fmaf(y, fmaf(y, fmaf(y, -184.9052456f,
                        77392.33017f), -11214424.18f), 651619640.7f),
                        -13362590354.0f), 57568490574.0f);
        float den = fmaf(y, fmaf(y, fmaf(y, fmaf(y, fmaf(y, 1.0f,
                        267.8532712f), 59272.64853f), 9494680.718f),
                        1029532985.0f), 57568490411.0f);
        res = num * rcp_ap(den);
    } else {
        float inv = rcp_ap(ax);
        float z   = 8.0f * inv;
        float y2  = z * z;
        float xx  = ax - 0.785398164f;
        float qn  = rintf(xx * INV2PI);
        float t   = fmaf(qn, NC1, xx);
        t         = fmaf(qn, NC2, t);
        float sn = __sinf(t);
        float cs = __cosf(t);
        float p0 = fmaf(y2, fmaf(y2, fmaf(y2, fmaf(y2, 0.2093887211e-6f,
                        -0.2073370639e-5f), 0.2734510407e-4f),
                        -0.1098628627e-2f), 1.0f);
        float q0 = fmaf(y2, fmaf(y2, fmaf(y2, fmaf(y2, -0.934935152e-7f,
                        0.7621095161e-6f), -0.6911147651e-5f),
                        0.1430488765e-3f), -0.1562499995e-1f);
        float amp = sqrt_ap(0.636619772f * inv);
        res = amp * fmaf(cs, p0, -(z * sn * q0));
    }
    return res * INV2PI;
}

// Fused fast path for a packed pair. Requires both s >= SMALLS.
// out = rsqrt(r*CINV) * cos(xx + i0*CQZ); p0 correction dropped (norm-err
// contribution ~3.3e-5), constant amplitude folded into the rsqrt argument.
__device__ __forceinline__ uint64_t pair_fast(uint64_t s) {
    float s0, s1; upk2(s, s0, s1);
    uint64_t i0 = pk2(rsq_ap(s0), rsq_ap(s1));        // ~1/sqrt(s)  [2 MUFU]
    uint64_t r0 = mul2(s, i0);                        // ~sqrt(s)
    uint64_t d  = fma2(i0, r0, c2(-1.0f));            // s*i0^2 - 1 (FMA-exact)
    uint64_t w  = mul2(r0, d);
    uint64_t r  = fma2(w, c2(-0.5f), r0);             // refined sqrt(s)
    uint64_t xx = fma2(r, c2(1000.0f), c2(-0.785398164f));
    uint64_t tp = fma2(i0, c2(CQZ), xx);              // + z*q0 phase fold
    uint64_t rc = mul2(r, c2(CINV));
    float rA, rB; upk2(rc, rA, rB);
    uint64_t am = pk2(rsq_ap(rA), rsq_ap(rB));        // CSQA*r^{-1/2} [2 MUFU]
    float t0, t1; upk2(tp, t0, t1);
    uint64_t cs = pk2(cos_ap(t0), cos_ap(t1));        // HW range red. [2 MUFU]
    return mul2(am, cs);
}

// One 4-column group. Slow path recomputes coords from px/py (keeps the
// packed diffs' live ranges out of the branch — measured best structure).
__device__ __forceinline__ ulonglong2 group4p(ulonglong2 ux, ulonglong2 uy,
                                              uint64_t npx, uint64_t npy,
                                              float px, float py) {
    uint64_t dxA = add2(ux.x, npx);
    uint64_t dyA = add2(uy.x, npy);
    uint64_t dxB = add2(ux.y, npx);
    uint64_t dyB = add2(uy.y, npy);
    uint64_t sA = fma2(dxA, dxA, mul2(dyA, dyA));
    uint64_t sB = fma2(dxB, dxB, mul2(dyB, dyB));
    float s0, s1, s2, s3;
    upk2(sA, s0, s1); upk2(sB, s2, s3);
    ulonglong2 o;
    if (__builtin_expect(fminf(fminf(s0, s1), fminf(s2, s3)) < SMALLS, 0)) {
        float x0, x1, x2, x3, y0, y1, y2, y3;
        upk2(ux.x, x0, x1); upk2(ux.y, x2, x3);
        upk2(uy.x, y0, y1); upk2(uy.y, y2, y3);
        o.x = pk2(j0_slow(px - x0, py - y0), j0_slow(px - x1, py - y1));
        o.y = pk2(j0_slow(px - x2, py - y2), j0_slow(px - x3, py - y3));
    } else {
        o.x = pair_fast(sA);
        o.y = pair_fast(sB);
    }
    return o;
}

// Column-split kernel: gridDim.y=2 halves of the source set, 20 KB smem each,
// 6 blocks/SM. 2 rows x 4 cols micro-tile, 128-bit LDS/STG end-to-end.
__global__ __launch_bounds__(BLOCK, 6)
void pikf_packed_kernel(const float2* __restrict__ p,
                        const float2* __restrict__ src,
                        float* __restrict__ out, int N, int M, int chunk) {
    __shared__ float sx[HALF];
    __shared__ float sy[HALF];

    const int base = blockIdx.y * chunk;
    const int cnt  = min(chunk, M - base);
    for (int i = threadIdx.x; i < cnt; i += BLOCK) {
        float2 v = src[base + i];
        sx[i] = v.x;
        sy[i] = v.y;
    }
    __syncthreads();

    const int C4 = cnt >> 2;
    const ulonglong2* sx4 = (const ulonglong2*)sx;
    const ulonglong2* sy4 = (const ulonglong2*)sy;

    const int row0 = blockIdx.x * ROWS;
    #pragma unroll 1
    for (int rp = 0; rp < ROWS / 2; ++rp) {
        int n0 = row0 + rp * 2;
        if (n0 >= N) return;
        int n1 = n0 + 1;
        float2 pp0 = p[n0];
        uint64_t npx0 = c2(-pp0.x), npy0 = c2(-pp0.y);
        ulonglong2* o40 = (ulonglong2*)(out + (size_t)n0 * M + base);

        if (n1 < N) {
            float2 pp1 = p[n1];
            uint64_t npx1 = c2(-pp1.x), npy1 = c2(-pp1.y);
            ulonglong2* o41 = (ulonglong2*)(out + (size_t)n1 * M + base);
            #pragma unroll 2
            for (int j = threadIdx.x; j < C4; j += BLOCK) {
                ulonglong2 ux = sx4[j];
                ulonglong2 uy = sy4[j];
                o40[j] = group4p(ux, uy, npx0, npy0, pp0.x, pp0.y);
                o41[j] = group4p(ux, uy, npx1, npy1, pp1.x, pp1.y);
            }
        } else {
            for (int j = threadIdx.x; j < C4; j += BLOCK) {
                ulonglong2 ux = sx4[j];
                ulonglong2 uy = sy4[j];
                o40[j] = group4p(ux, uy, npx0, npy0, pp0.x, pp0.y);
            }
        }
    }
}

// scalar fallback for odd M / huge M
__global__ __launch_bounds__(BLOCK)
void pikf_scalar_kernel(const float2* __restrict__ p,
                        const float2* __restrict__ src,
                        float* __restrict__ out, int N, int M) {
    int row0 = blockIdx.x * ROWS;
    for (int rr = 0; rr < ROWS; ++rr) {
        int n = row0 + rr;
        if (n >= N) return;
        float2 pp = p[n];
        for (int m = threadIdx.x; m < M; m += BLOCK) {
            float2 v = __ldg(&src[m]);
            out[(size_t)n * M + m] = j0_slow(pp.x - v.x, pp.y - v.y);
        }
    }
}

extern "C" void kernel_launch(void* const* d_in, const int* in_sizes, int n_in,
                              void* d_out, int out_size) {
    const float2* p   = (const float2*)d_in[0];
    const float2* src = (const float2*)d_in[1];
    float* out = (float*)d_out;
    int N = in_sizes[0] / 2;
    int M = in_sizes[1] / 2;
    int gx = (N + ROWS - 1) / ROWS;
    // column split into 2 chunks; M % 8 == 0 keeps both halves 16B-aligned.
    if (M <= MAXM && (M % 8) == 0 && (M / 2) <= HALF) {
        int chunk = M / 2;
        dim3 grid(gx, 2);
        pikf_packed_kernel<<<grid, BLOCK>>>(p, src, out, N, M, chunk);
    } else {
        pikf_scalar_kernel<<<gx, BLOCK>>>(p, src, out, N, M);
    }
}

// round 16
// speedup vs baseline: 1.2219x; 1.0394x over previous
#include <cuda_runtime.h>
#include <cuda_bf16.h>
#include <cstdint>

#define BLOCK 256
#define ROWS 8
#define HALF 2560          // max sources staged per block (column split)
#define MAXM 5120

// ---------- packed f32x2 helpers (Blackwell) ----------
__device__ __forceinline__ uint64_t pk2(float x, float y) {
    uint64_t r; asm("mov.b64 %0, {%1, %2};" : "=l"(r) : "f"(x), "f"(y)); return r;
}
__device__ __forceinline__ void upk2(uint64_t v, float& x, float& y) {
    asm("mov.b64 {%0, %1}, %2;" : "=f"(x), "=f"(y) : "l"(v));
}
__device__ __forceinline__ uint64_t add2(uint64_t a, uint64_t b) {
    uint64_t d; asm("add.rn.f32x2 %0, %1, %2;" : "=l"(d) : "l"(a), "l"(b)); return d;
}
__device__ __forceinline__ uint64_t mul2(uint64_t a, uint64_t b) {
    uint64_t d; asm("mul.rn.f32x2 %0, %1, %2;" : "=l"(d) : "l"(a), "l"(b)); return d;
}
__device__ __forceinline__ uint64_t fma2(uint64_t a, uint64_t b, uint64_t c) {
    uint64_t d; asm("fma.rn.f32x2 %0, %1, %2, %3;" : "=l"(d) : "l"(a), "l"(b), "l"(c)); return d;
}
__device__ __forceinline__ uint64_t c2(float k) { return pk2(k, k); }

// ---------- scalar approx primitives ----------
__device__ __forceinline__ float rsq_ap(float x){ float y; asm("rsqrt.approx.f32 %0, %1;" : "=f"(y) : "f"(x)); return y; }
__device__ __forceinline__ float sqrt_ap(float x){ float y; asm("sqrt.approx.f32 %0, %1;" : "=f"(y) : "f"(x)); return y; }
__device__ __forceinline__ float cos_ap(float x){ float y; asm("cos.approx.f32 %0, %1;" : "=f"(y) : "f"(x)); return y; }
__device__ __forceinline__ float rcp_ap(float x){ float y; asm("rcp.approx.f32 %0, %1;" : "=f"(y) : "f"(x)); return y; }

// ---------- constants ----------
#define INV2PI  0.15915494309189535f
#define NC1     (-6.28125f)
#define NC2     (-1.9353071795864769e-3f)
#define SMALLS  (6.4e-5f)               // (8/1000)^2 : ax<8  <=>  s<SMALLS
#define CQZ     (-1.2499999960e-4f)     // Q0C * 8e-3 (phase-folded quadrature)
// amp = CSQA * s^{-1/4} = sqrt(CSQA^2 * i0);  CSQA^2 = 0.636619772e-3/(2pi)^2
#define CSQA2   (1.61257598e-5f)

// ---------- accurate scalar fallback (rare small-argument groups) ----------
__device__ __noinline__ float j0_slow(float dx, float dy) {
    float s  = fmaf(dx, dx, dy * dy);
    float r  = __fsqrt_rn(s);
    float ax = 1000.0f * r;
    float res;
    if (ax < 8.0f) {
        float y = ax * ax;
        float num = fmaf(y, fmaf(y, fmaf(y, fmaf(y, fmaf(y, -184.9052456f,
                        77392.33017f), -11214424.18f), 651619640.7f),
                        -13362590354.0f), 57568490574.0f);
        float den = fmaf(y, fmaf(y, fmaf(y, fmaf(y, fmaf(y, 1.0f,
                        267.8532712f), 59272.64853f), 9494680.718f),
                        1029532985.0f), 57568490411.0f);
        res = num * rcp_ap(den);
    } else {
        float inv = rcp_ap(ax);
        float z   = 8.0f * inv;
        float y2  = z * z;
        float xx  = ax - 0.785398164f;
        float qn  = rintf(xx * INV2PI);
        float t   = fmaf(qn, NC1, xx);
        t         = fmaf(qn, NC2, t);
        float sn = __sinf(t);
        float cs = __cosf(t);
        float p0 = fmaf(y2, fmaf(y2, fmaf(y2, fmaf(y2, 0.2093887211e-6f,
                        -0.2073370639e-5f), 0.2734510407e-4f),
                        -0.1098628627e-2f), 1.0f);
        float q0 = fmaf(y2, fmaf(y2, fmaf(y2, fmaf(y2, -0.934935152e-7f,
                        0.7621095161e-6f), -0.6911147651e-5f),
                        0.1430488765e-3f), -0.1562499995e-1f);
        float amp = sqrt_ap(0.636619772f * inv);
        res = amp * fmaf(cs, p0, -(z * sn * q0));
    }
    return res * INV2PI;
}

// Fused fast path for a packed pair. Requires both s >= SMALLS.
// out = sqrt(CSQA2*i0) * cos(1000*s*i0 - pi/4 + i0*CQZ)
// (sqrt refinement dropped: raw r0 = s*rsq(s) carries ~2 ulp, phase jitter
//  ~2-5e-4 rad -> norm rel_err ~3-5e-4, inside the 1e-3 budget)
__device__ __forceinline__ uint64_t pair_fast(uint64_t s) {
    float s0, s1; upk2(s, s0, s1);
    uint64_t i0 = pk2(rsq_ap(s0), rsq_ap(s1));        // ~1/sqrt(s)  [2 MUFU]
    uint64_t r0 = mul2(s, i0);                        // ~sqrt(s)
    uint64_t xx = fma2(r0, c2(1000.0f), c2(-0.785398164f));
    uint64_t tp = fma2(i0, c2(CQZ), xx);              // + z*q0 phase fold
    uint64_t sc = mul2(i0, c2(CSQA2));
    float a0, a1; upk2(sc, a0, a1);
    uint64_t am = pk2(sqrt_ap(a0), sqrt_ap(a1));      // amp = CSQA*s^-1/4 [2 MUFU]
    float t0, t1; upk2(tp, t0, t1);
    uint64_t cs = pk2(cos_ap(t0), cos_ap(t1));        // HW range red. [2 MUFU]
    return mul2(am, cs);
}

// One 4-column group. Slow path recomputes coords from px/py (keeps the
// packed diffs' live ranges out of the branch — measured best structure).
__device__ __forceinline__ ulonglong2 group4p(ulonglong2 ux, ulonglong2 uy,
                                              uint64_t npx, uint64_t npy,
                                              float px, float py) {
    uint64_t dxA = add2(ux.x, npx);
    uint64_t dyA = add2(uy.x, npy);
    uint64_t dxB = add2(ux.y, npx);
    uint64_t dyB = add2(uy.y, npy);
    uint64_t sA = fma2(dxA, dxA, mul2(dyA, dyA));
    uint64_t sB = fma2(dxB, dxB, mul2(dyB, dyB));
    float s0, s1, s2, s3;
    upk2(sA, s0, s1); upk2(sB, s2, s3);
    ulonglong2 o;
    if (__builtin_expect(fminf(fminf(s0, s1), fminf(s2, s3)) < SMALLS, 0)) {
        float x0, x1, x2, x3, y0, y1, y2, y3;
        upk2(ux.x, x0, x1); upk2(ux.y, x2, x3);
        upk2(uy.x, y0, y1); upk2(uy.y, y2, y3);
        o.x = pk2(j0_slow(px - x0, py - y0), j0_slow(px - x1, py - y1));
        o.y = pk2(j0_slow(px - x2, py - y2), j0_slow(px - x3, py - y3));
    } else {
        o.x = pair_fast(sA);
        o.y = pair_fast(sB);
    }
    return o;
}

// Column-split kernel: gridDim.y=2 halves of the source set, 20 KB smem each,
// 6 blocks/SM. 2 rows x 4 cols micro-tile, 128-bit LDS/STG end-to-end.
__global__ __launch_bounds__(BLOCK, 6)
void pikf_packed_kernel(const float2* __restrict__ p,
                        const float2* __restrict__ src,
                        float* __restrict__ out, int N, int M, int chunk) {
    __shared__ float sx[HALF];
    __shared__ float sy[HALF];

    const int base = blockIdx.y * chunk;
    const int cnt  = min(chunk, M - base);
    for (int i = threadIdx.x; i < cnt; i += BLOCK) {
        float2 v = src[base + i];
        sx[i] = v.x;
        sy[i] = v.y;
    }
    __syncthreads();

    const int C4 = cnt >> 2;
    const ulonglong2* sx4 = (const ulonglong2*)sx;
    const ulonglong2* sy4 = (const ulonglong2*)sy;

    const int row0 = blockIdx.x * ROWS;
    #pragma unroll 1
    for (int rp = 0; rp < ROWS / 2; ++rp) {
        int n0 = row0 + rp * 2;
        if (n0 >= N) return;
        int n1 = n0 + 1;
        float2 pp0 = p[n0];
        uint64_t npx0 = c2(-pp0.x), npy0 = c2(-pp0.y);
        ulonglong2* o40 = (ulonglong2*)(out + (size_t)n0 * M + base);

        if (n1 < N) {
            float2 pp1 = p[n1];
            uint64_t npx1 = c2(-pp1.x), npy1 = c2(-pp1.y);
            ulonglong2* o41 = (ulonglong2*)(out + (size_t)n1 * M + base);
            #pragma unroll 2
            for (int j = threadIdx.x; j < C4; j += BLOCK) {
                ulonglong2 ux = sx4[j];
                ulonglong2 uy = sy4[j];
                o40[j] = group4p(ux, uy, npx0, npy0, pp0.x, pp0.y);
                o41[j] = group4p(ux, uy, npx1, npy1, pp1.x, pp1.y);
            }
        } else {
            for (int j = threadIdx.x; j < C4; j += BLOCK) {
                ulonglong2 ux = sx4[j];
                ulonglong2 uy = sy4[j];
                o40[j] = group4p(ux, uy, npx0, npy0, pp0.x, pp0.y);
            }
        }
    }
}

// scalar fallback for odd M / huge M
__global__ __launch_bounds__(BLOCK)
void pikf_scalar_kernel(const float2* __restrict__ p,
                        const float2* __restrict__ src,
                        float* __restrict__ out, int N, int M) {
    int row0 = blockIdx.x * ROWS;
    for (int rr = 0; rr < ROWS; ++rr) {
        int n = row0 + rr;
        if (n >= N) return;
        float2 pp = p[n];
        for (int m = threadIdx.x; m < M; m += BLOCK) {
            float2 v = __ldg(&src[m]);
            out[(size_t)n * M + m] = j0_slow(pp.x - v.x, pp.y - v.y);
        }
    }
}

extern "C" void kernel_launch(void* const* d_in, const int* in_sizes, int n_in,
                              void* d_out, int out_size) {
    const float2* p   = (const float2*)d_in[0];
    const float2* src = (const float2*)d_in[1];
    float* out = (float*)d_out;
    int N = in_sizes[0] / 2;
    int M = in_sizes[1] / 2;
    int gx = (N + ROWS - 1) / ROWS;
    // column split into 2 chunks; M % 8 == 0 keeps both halves 16B-aligned.
    if (M <= MAXM && (M % 8) == 0 && (M / 2) <= HALF) {
        int chunk = M / 2;
        dim3 grid(gx, 2);
        pikf_packed_kernel<<<grid, BLOCK>>>(p, src, out, N, M, chunk);
    } else {
        pikf_scalar_kernel<<<gx, BLOCK>>>(p, src, out, N, M);
    }
}